// round 4
// baseline (speedup 1.0000x reference)
#include <cuda_runtime.h>

// Problem constants (match reference)
#define BATCH   512
#define IN_DIM  784
#define OUT_DIM 10
#define STEPS   200
#define NSCAN   (STEPS - 1)   // 199 drive slices / scan steps
#define IHALF   (IN_DIM / 2)  // 392 = 49 batches of 8
#define NBATCH  (IHALF / 8)   // 49

// LIF constants
#define A_M     0.995f        // 1 - DT/TAU_M
#define G_M     0.005f        // DT/TAU_M
#define A_S     0.98f         // 1 - DT/TAU_S

__device__ __forceinline__ float ldcs(const float* p) {
    float v;
    asm volatile("ld.global.cs.f32 %0, [%1];" : "=f"(v) : "l"(p));
    return v;
}

__device__ __forceinline__ void addp(unsigned long long& acc, unsigned long long w) {
    asm("add.rn.f32x2 %0, %1, %2;" : "=l"(acc) : "l"(acc), "l"(w));
}

__global__ __launch_bounds__(512, 3)
void snn_kernel(const float* __restrict__ x,     // [B, IN, STEPS]
                const float* __restrict__ w,     // [O, IN]
                float* __restrict__ out)         // [B, O]
{
    // wsh padded row stride 10 floats (40 B, 8-B aligned for LDS.64)
    __shared__ float wsh[IN_DIM * OUT_DIM];      // [i][o], 31360 B
    __shared__ float drv[NSCAN * OUT_DIM];       // [t][o], 7960 B

    const int b    = blockIdx.x;
    const int tid  = threadIdx.x;
    const int half = tid >> 8;                   // 0 or 1: which i-half
    const int t    = tid & 255;                  // time index within half

    // Load weights into smem transposed: wsh[i*10 + o] = w[o*784 + i]
    for (int k = tid; k < IN_DIM * OUT_DIM; k += blockDim.x) {
        int i = k / OUT_DIM;
        int o = k - i * OUT_DIM;
        wsh[k] = w[o * IN_DIM + i];
    }
    __syncthreads();

    const float* xb = x + (size_t)b * IN_DIM * STEPS;

    // 5 packed f32x2 accumulators = 10 output channels
    unsigned long long acc[5] = {0ull, 0ull, 0ull, 0ull, 0ull};

    if (t < NSCAN) {
        const int ibase = half * IHALF;
        const float* xh = xb + (size_t)ibase * STEPS + t;

        float vA[8], vB[8];

        // Consume one batch of 8 prefetched values
        #define PROCESS(V, K)                                                     \
            do {                                                                  \
                const int rb_ = (ibase + (K) * 8);                                \
                _Pragma("unroll")                                                 \
                for (int j = 0; j < 8; j++) {                                     \
                    if (__float_as_uint((V)[j]) != 0u) {                          \
                        const unsigned long long* wr =                            \
                            (const unsigned long long*)&wsh[(rb_ + j) * OUT_DIM]; \
                        _Pragma("unroll")                                         \
                        for (int p = 0; p < 5; p++) addp(acc[p], wr[p]);          \
                    }                                                             \
                }                                                                 \
            } while (0)

        #define LOAD(V, K)                                                        \
            do {                                                                  \
                const float* bp_ = xh + (size_t)((K) * 8) * STEPS;                \
                _Pragma("unroll")                                                 \
                for (int j = 0; j < 8; j++)                                       \
                    (V)[j] = ldcs(bp_ + (size_t)j * STEPS);                       \
            } while (0)

        LOAD(vA, 0);
        // 48 batches in software-pipelined pairs; batch 48 in epilogue
        #pragma unroll 1
        for (int k = 0; k < NBATCH - 1; k += 2) {
            LOAD(vB, k + 1);
            PROCESS(vA, k);
            LOAD(vA, k + 2);      // k+2 <= 48 always (k <= 46)
            PROCESS(vB, k + 1);
        }
        PROCESS(vA, NBATCH - 1);

        #undef PROCESS
        #undef LOAD
    }

    // Combine the two i-half partials through smem.
    if (half == 1 && t < NSCAN) {
        #pragma unroll
        for (int p = 0; p < 5; p++) {
            float lo = __uint_as_float((unsigned)(acc[p] & 0xFFFFFFFFull));
            float hi = __uint_as_float((unsigned)(acc[p] >> 32));
            drv[t * OUT_DIM + 2 * p]     = lo;
            drv[t * OUT_DIM + 2 * p + 1] = hi;
        }
    }
    __syncthreads();
    if (half == 0 && t < NSCAN) {
        #pragma unroll
        for (int p = 0; p < 5; p++) {
            float lo = __uint_as_float((unsigned)(acc[p] & 0xFFFFFFFFull));
            float hi = __uint_as_float((unsigned)(acc[p] >> 32));
            drv[t * OUT_DIM + 2 * p]     += lo;
            drv[t * OUT_DIM + 2 * p + 1] += hi;
        }
    }
    __syncthreads();

    // Sequential LIF scan per output neuron; record first spike time.
    if (tid < OUT_DIM) {
        const int o = tid;
        float V = 0.0f, I = 0.0f;
        int fst = 0;
        for (int tt = 0; tt < NSCAN; tt++) {
            float Vn = A_M * V + G_M * I;
            float In = A_S * I + drv[tt * OUT_DIM + o];
            if (Vn > 1.0f) { fst = tt + 1; break; }
            V = Vn;
            I = In;
        }
        out[b * OUT_DIM + o] = (fst == 0) ? (float)(STEPS - 1) : (float)fst;
    }
}

extern "C" void kernel_launch(void* const* d_in, const int* in_sizes, int n_in,
                              void* d_out, int out_size)
{
    const float* x = (const float*)d_in[0];   // [512, 784, 200]
    const float* w = (const float*)d_in[1];   // [10, 784]
    float* out = (float*)d_out;               // [512, 10]
    snn_kernel<<<BATCH, 512>>>(x, w, out);
}